// round 9
// baseline (speedup 1.0000x reference)
#include <cuda_runtime.h>
#include <math.h>

#define T_ALL 128
#define T_STEPS 127
#define BSZ 256
#define DD 512
#define HH 1024
#define OO 20
#define KC 320                     // Eigen gebp kc panel boundary (confirmed R5)
#define TCHUNK 16                  // timesteps per in_gemm chunk

__device__ __constant__ float c_ALPHA = 0.95122942450071400909f; // fp32(exp(-1/20))
__device__ __constant__ float c_KAPPA = 0.95122942450071400909f;
#define THRv 1.0f

// ---- scratch (device globals; no allocation allowed) ----
__device__ float g_xin[(size_t)T_STEPS * BSZ * HH];   // 133 MB
__device__ float g_WT[HH * HH];        // WT[j][h] = w_rec_eff[h][j] (diag zeroed)
__device__ int   g_ready;              // chunk-completion flag (monotonic per launch)

// packed dual fp32 FMA (per-lane IEEE rn — bit-exact per chain)
#define FMA2(d_, a_, b_) \
    asm("fma.rn.f32x2 %0, %1, %2, %3;" : "=l"(d_) : "l"(a_), "l"(b_), "l"(d_))

__device__ __forceinline__ float2 unpack2(unsigned long long u) {
    float2 f;
    asm("mov.b64 {%0, %1}, %2;" : "=f"(f.x), "=f"(f.y) : "l"(u));
    return f;
}

// ============================================================
__global__ void set_flag(int v) { g_ready = v; }
__global__ void marker(int v)   { atomicExch(&g_ready, v); }

// ============================================================
// prep: transposed, diagonal-zeroed recurrent weights
// ============================================================
__global__ void __launch_bounds__(256) prep_k(const float* __restrict__ w_rec) {
    int idx = blockIdx.x * 256 + threadIdx.x;
    int stride = gridDim.x * 256;
    for (int i = idx; i < HH * HH; i += stride) {
        int j = i / HH, h = i % HH;
        g_WT[i] = (h == j) ? 0.0f : w_rec[(size_t)h * HH + j];
    }
}

// ============================================================
// input GEMM chunk (bit-exact ascending-k chain, kc=320 fold):
// 128m x 128n tile, BK=8 double-buffered, 256 threads, 8x8 microtile
// computed via fma.rn.f32x2 (A duplicated in smem -> packed broadcast pairs)
// ============================================================
__global__ void __launch_bounds__(256) in_gemm(const float* __restrict__ x,
                                               const float* __restrict__ w_in,
                                               int m_base) {
    __shared__ float As2[2][8][256];    // duplicated: As2[d][2m]=As2[d][2m+1]=A[m]
    __shared__ float Bs[2][8][128];
    const int tid = threadIdx.x;
    const int m0 = m_base + blockIdx.y * 128;
    const int n0 = blockIdx.x * 128;

    const int lr = tid >> 1;            // 0..127
    const int lk = (tid & 1) * 4;       // 0 or 4
    const int tm = (tid >> 4) * 8;      // 0..120
    const int tn = (tid & 15) * 8;      // 0..120

    const float* Ap = x + (size_t)(m0 + lr) * DD + lk;
    const float* Bp = w_in + (size_t)(n0 + lr) * DD + lk;

    float4 a  = __ldcs((const float4*)Ap);        // streaming: protect L2 for g_WT
    float4 bb = *(const float4*)Bp;
    As2[0][lk + 0][2 * lr] = a.x; As2[0][lk + 0][2 * lr + 1] = a.x;
    As2[0][lk + 1][2 * lr] = a.y; As2[0][lk + 1][2 * lr + 1] = a.y;
    As2[0][lk + 2][2 * lr] = a.z; As2[0][lk + 2][2 * lr + 1] = a.z;
    As2[0][lk + 3][2 * lr] = a.w; As2[0][lk + 3][2 * lr + 1] = a.w;
    Bs[0][lk + 0][lr] = bb.x; Bs[0][lk + 1][lr] = bb.y;
    Bs[0][lk + 2][lr] = bb.z; Bs[0][lk + 3][lr] = bb.w;
    __syncthreads();

    unsigned long long acc2[8][4];      // [i][jpair], lanes = cols (tn+2jp, tn+2jp+1)
#pragma unroll
    for (int i = 0; i < 8; i++)
#pragma unroll
        for (int jp = 0; jp < 4; jp++) acc2[i][jp] = 0ULL;

    int s = 0;
    for (int k0 = 0; k0 < DD; k0 += 8) {
        const int nk = k0 + 8;
        if (nk < DD) {                  // prefetch next tile into registers
            a  = __ldcs((const float4*)(Ap + nk));
            bb = *(const float4*)(Bp + nk);
        }
#pragma unroll
        for (int d = 0; d < 8; d++) {   // ascending k
            ulonglong2 ar01 = *(const ulonglong2*)(&As2[s][d][2 * tm + 0]);
            ulonglong2 ar23 = *(const ulonglong2*)(&As2[s][d][2 * tm + 4]);
            ulonglong2 ar45 = *(const ulonglong2*)(&As2[s][d][2 * tm + 8]);
            ulonglong2 ar67 = *(const ulonglong2*)(&As2[s][d][2 * tm + 12]);
            ulonglong2 br01 = *(const ulonglong2*)(&Bs[s][d][tn + 0]);
            ulonglong2 br23 = *(const ulonglong2*)(&Bs[s][d][tn + 4]);
            unsigned long long ar[8] = {ar01.x, ar01.y, ar23.x, ar23.y,
                                        ar45.x, ar45.y, ar67.x, ar67.y};
            unsigned long long br[4] = {br01.x, br01.y, br23.x, br23.y};
#pragma unroll
            for (int i = 0; i < 8; i++)
#pragma unroll
                for (int jp = 0; jp < 4; jp++)
                    FMA2(acc2[i][jp], ar[i], br[jp]);
        }
        if (nk == KC) {                 // stage panel 0 to global, restart chain
#pragma unroll
            for (int i = 0; i < 8; i++) {
                float* dst = g_xin + (size_t)(m0 + tm + i) * HH + n0 + tn;
                float2 u0 = unpack2(acc2[i][0]), u1 = unpack2(acc2[i][1]);
                float2 u2 = unpack2(acc2[i][2]), u3 = unpack2(acc2[i][3]);
                *(float4*)(dst + 0) = make_float4(u0.x, u0.y, u1.x, u1.y);
                *(float4*)(dst + 4) = make_float4(u2.x, u2.y, u3.x, u3.y);
#pragma unroll
                for (int jp = 0; jp < 4; jp++) acc2[i][jp] = 0ULL;
            }
        }
        if (nk < DD) {                  // store prefetched tile to other buffer
            As2[s ^ 1][lk + 0][2 * lr] = a.x; As2[s ^ 1][lk + 0][2 * lr + 1] = a.x;
            As2[s ^ 1][lk + 1][2 * lr] = a.y; As2[s ^ 1][lk + 1][2 * lr + 1] = a.y;
            As2[s ^ 1][lk + 2][2 * lr] = a.z; As2[s ^ 1][lk + 2][2 * lr + 1] = a.z;
            As2[s ^ 1][lk + 3][2 * lr] = a.w; As2[s ^ 1][lk + 3][2 * lr + 1] = a.w;
            Bs[s ^ 1][lk + 0][lr] = bb.x; Bs[s ^ 1][lk + 1][lr] = bb.y;
            Bs[s ^ 1][lk + 2][lr] = bb.z; Bs[s ^ 1][lk + 3][lr] = bb.w;
        }
        __syncthreads();
        s ^= 1;
    }

    // fold: xin = fadd(p0, p1)  (exact Eigen panel fold)
#pragma unroll
    for (int i = 0; i < 8; i++) {
        float* dst = g_xin + (size_t)(m0 + tm + i) * HH + n0 + tn;
        float4 p0a = *(const float4*)(dst + 0);
        float4 p0b = *(const float4*)(dst + 4);
        float2 u0 = unpack2(acc2[i][0]), u1 = unpack2(acc2[i][1]);
        float2 u2 = unpack2(acc2[i][2]), u3 = unpack2(acc2[i][3]);
        float4 oa, ob;
        oa.x = __fadd_rn(p0a.x, u0.x); oa.y = __fadd_rn(p0a.y, u0.y);
        oa.z = __fadd_rn(p0a.z, u1.x); oa.w = __fadd_rn(p0a.w, u1.y);
        ob.x = __fadd_rn(p0b.x, u2.x); ob.y = __fadd_rn(p0b.y, u2.y);
        ob.z = __fadd_rn(p0b.z, u3.x); ob.w = __fadd_rn(p0b.w, u3.y);
        __stcs((float4*)(dst + 0), oa);
        __stcs((float4*)(dst + 4), ob);
    }
}

// ============================================================
// persistent per-batch-row kernel: block b runs ALL 127 steps,
// then softmaxes its 128 output rows. Bit-exact v-path.
// ============================================================
__global__ void __launch_bounds__(256) step_all(const float* __restrict__ w_out,
                                                float* __restrict__ out) {
    const int b = blockIdx.x;
    const int tid = threadIdx.x;
    const int lane = tid & 31, wid = tid >> 5;
    const int h4 = tid * 4;

    __shared__ int lists[2][HH];
    __shared__ int s_po[5];
    __shared__ int s_wsum[8], s_woff[8];
    __shared__ int s_total;
    __shared__ float s_red[OO][9];

    float v0 = 0.f, v1 = 0.f, v2 = 0.f, v3 = 0.f;
    float vo = 0.f;

    if (tid < 5) s_po[tid] = 0;
    if (tid < OO) out[(size_t)b * OO + tid] = 0.f;   // row t=0
    __syncthreads();

    for (int t = 0; t < T_STEPS; t++) {
        if ((t & (TCHUNK - 1)) == 0) {
            if (tid == 0) {
                const int need = (t >> 4) + 1;
                while (*((volatile int*)&g_ready) < need) __nanosleep(200);
            }
            __syncthreads();
        }

        const int* act = lists[t & 1];
        int* nxt = lists[(t + 1) & 1];

        // ---- sparse recurrent sum: exact per-panel chains, MLP-8 ----
        float tot0 = 0.f, tot1 = 0.f, tot2 = 0.f, tot3 = 0.f;
#pragma unroll 1
        for (int p = 0; p < 4; p++) {
            const int beg = s_po[p], end = s_po[p + 1];
            float a0 = 0.f, a1 = 0.f, a2 = 0.f, a3 = 0.f;
            int i = beg;
            for (; i + 8 <= end; i += 8) {
                float4 w[8];
#pragma unroll
                for (int q = 0; q < 8; q++)
                    w[q] = *(const float4*)(g_WT + (size_t)act[i + q] * HH + h4);
#pragma unroll
                for (int q = 0; q < 8; q++) {
                    a0 = __fadd_rn(a0, w[q].x);
                    a1 = __fadd_rn(a1, w[q].y);
                    a2 = __fadd_rn(a2, w[q].z);
                    a3 = __fadd_rn(a3, w[q].w);
                }
            }
            for (; i < end; i++) {
                const float4 w = *(const float4*)(g_WT + (size_t)act[i] * HH + h4);
                a0 = __fadd_rn(a0, w.x);
                a1 = __fadd_rn(a1, w.y);
                a2 = __fadd_rn(a2, w.z);
                a3 = __fadd_rn(a3, w.w);
            }
            tot0 = __fadd_rn(tot0, a0);
            tot1 = __fadd_rn(tot1, a1);
            tot2 = __fadd_rn(tot2, a2);
            tot3 = __fadd_rn(tot3, a3);
        }

        // ---- v update ----
        const float4 xi = __ldcs((const float4*)(g_xin + (size_t)t * BSZ * HH
                                                 + (size_t)b * HH + h4));
        const float zp0 = (v0 > THRv) ? 1.f : 0.f;
        const float zp1 = (v1 > THRv) ? 1.f : 0.f;
        const float zp2 = (v2 > THRv) ? 1.f : 0.f;
        const float zp3 = (v3 > THRv) ? 1.f : 0.f;

        v0 = __fsub_rn(__fadd_rn(__fmaf_rn(c_ALPHA, v0, tot0), xi.x), zp0);
        v1 = __fsub_rn(__fadd_rn(__fmaf_rn(c_ALPHA, v1, tot1), xi.y), zp1);
        v2 = __fsub_rn(__fadd_rn(__fmaf_rn(c_ALPHA, v2, tot2), xi.z), zp2);
        v3 = __fsub_rn(__fadd_rn(__fmaf_rn(c_ALPHA, v3, tot3), xi.w), zp3);

        const bool z0 = v0 > THRv, z1 = v1 > THRv, z2 = v2 > THRv, z3 = v3 > THRv;
        const int cnt = (int)z0 + (int)z1 + (int)z2 + (int)z3;

        // ---- ordered block scan -> ascending active list for t+1 ----
        int s = cnt;
#pragma unroll
        for (int o = 1; o < 32; o <<= 1) {
            int u = __shfl_up_sync(0xffffffffu, s, o);
            if (lane >= o) s += u;
        }
        if (lane == 31) s_wsum[wid] = s;
        __syncthreads();
        if (wid == 0 && lane < 8) {
            int u = s_wsum[lane];
            int sc = u;
#pragma unroll
            for (int o = 1; o < 8; o <<= 1) {
                int q = __shfl_up_sync(0xffu, sc, o);
                if (lane >= o) sc += q;
            }
            s_woff[lane] = sc - u;
            if (lane == 7) s_total = sc;
        }
        __syncthreads();

        int o = s_woff[wid] + s - cnt;
        if (z0) nxt[o++] = h4 + 0;
        if (z1) nxt[o++] = h4 + 1;
        if (z2) nxt[o++] = h4 + 2;
        if (z3) nxt[o++] = h4 + 3;

        const int incl = s_woff[wid] + s;
        if (tid == 79)  s_po[1] = incl;       // h < 320
        if (tid == 159) s_po[2] = incl;       // h < 640
        if (tid == 239) s_po[3] = incl;       // h < 960
        if (tid == 255) { s_po[4] = incl; s_po[0] = 0; }
        __syncthreads();

        // ---- output projection over new spikes (order-free) ----
        const int total = s_total;
        if (tid < OO * 8) {
            const int oo = tid >> 3, c = tid & 7;
            const float* wr = w_out + (size_t)oo * HH;
            float acc = 0.f;
            for (int i = c; i < total; i += 8)
                acc += wr[nxt[i]];
            s_red[oo][c] = acc;
        }
        __syncthreads();
        if (tid < OO) {
            float ssum = s_red[tid][0];
#pragma unroll
            for (int c = 1; c < 8; c++) ssum += s_red[tid][c];
            vo = __fmaf_rn(c_KAPPA, vo, ssum);
            out[((size_t)(t + 1) * BSZ + b) * OO + tid] = vo;
        }
        __syncthreads();
    }

    // ---- softmax of this b's 128 rows (warp per row) ----
    __syncthreads();
    for (int r = wid; r < T_ALL; r += 8) {
        float* pr = out + ((size_t)r * BSZ + b) * OO;
        float vv = (lane < OO) ? pr[lane] : -INFINITY;
        float m = vv;
#pragma unroll
        for (int off = 16; off > 0; off >>= 1)
            m = fmaxf(m, __shfl_xor_sync(0xffffffff, m, off));
        float e = (lane < OO) ? expf(vv - m) : 0.f;
        float sm = e;
#pragma unroll
        for (int off = 16; off > 0; off >>= 1)
            sm += __shfl_xor_sync(0xffffffff, sm, off);
        if (lane < OO) pr[lane] = e / sm;
    }
}

// ============================================================
extern "C" void kernel_launch(void* const* d_in, const int* in_sizes, int n_in,
                              void* d_out, int out_size) {
    const float* x     = (const float*)d_in[0];  // [128,256,512]
    const float* w_in  = (const float*)d_in[1];  // [1024,512]
    const float* w_rec = (const float*)d_in[2];  // [1024,1024]
    const float* w_out = (const float*)d_in[3];  // [20,1024]
    float* out = (float*)d_out;                  // [128,256,20]

    static cudaStream_t s2 = nullptr;
    static cudaEvent_t eF = nullptr, eJ = nullptr;
    if (!s2) {
        cudaStreamCreateWithFlags(&s2, cudaStreamNonBlocking);
        cudaEventCreateWithFlags(&eF, cudaEventDisableTiming);
        cudaEventCreateWithFlags(&eJ, cudaEventDisableTiming);
    }

    set_flag<<<1, 1>>>(0);                       // reset chunk flag (per launch)
    prep_k<<<512, 256>>>(w_rec);

    // fork: input-GEMM chunks on side stream
    cudaEventRecord(eF, 0);
    cudaStreamWaitEvent(s2, eF, 0);
    for (int c = 0; c < 8; c++) {
        const int tcnt = (c == 7) ? (T_STEPS - 7 * TCHUNK) : TCHUNK;   // 15 for last
        const int yblocks = (tcnt * BSZ) / 128;
        in_gemm<<<dim3(HH / 128, yblocks), 256, 0, s2>>>(x, w_in, c * TCHUNK * BSZ);
        marker<<<1, 1, 0, s2>>>(c + 1);
    }
    cudaEventRecord(eJ, s2);

    // persistent recurrent scan (overlaps with in_gemm via flag gating)
    step_all<<<BSZ, 256>>>(w_out, out);

    cudaStreamWaitEvent(0, eJ, 0);               // join side stream into capture
}